// round 5
// baseline (speedup 1.0000x reference)
#include <cuda_runtime.h>
#include <float.h>

#define QD 8192   // QUANT_DIM (codebook size)
#define ED 512    // EMBED_DIM
#define NT 8192   // N_TOKENS
#define KSEL 8

// Scratch: weight.T [QD, ED] = 16 MB. Static __device__ global (no alloc).
__device__ float g_wT[(size_t)QD * ED];

// ---------------------------------------------------------------------------
// Kernel 1: tiled transpose weight[ED, QD] -> g_wT[QD, ED]
// ---------------------------------------------------------------------------
__global__ void transpose_kernel(const float* __restrict__ w) {
    __shared__ float tile[32][33];  // +1 pad: conflict-free
    int qx = blockIdx.x * 32 + threadIdx.x;  // quant col in w
    int ey = blockIdx.y * 32 + threadIdx.y;  // embed row in w
#pragma unroll
    for (int j = 0; j < 32; j += 8)
        tile[threadIdx.y + j][threadIdx.x] = w[(size_t)(ey + j) * QD + qx];
    __syncthreads();
    int ex = blockIdx.y * 32 + threadIdx.x;  // embed col in wT
    int qy = blockIdx.x * 32 + threadIdx.y;  // quant row in wT
#pragma unroll
    for (int j = 0; j < 32; j += 8)
        g_wT[(size_t)(qy + j) * ED + ex] = tile[threadIdx.x][threadIdx.y + j];
}

// ---------------------------------------------------------------------------
// Kernel 2: per-token top-8 + gather-sum from g_wT.
// One block (256 threads) per token.
// ALL comparisons use the strict total order lex(value desc, index asc) to
// match jax.lax.top_k tie-breaking (lower index wins on equal values).
// ---------------------------------------------------------------------------
__global__ __launch_bounds__(256) void topk_gather_kernel(
    const float* __restrict__ x, float* __restrict__ out) {
    const int n = blockIdx.x;
    const int t = threadIdx.x;

    __shared__ float s_val[256 * 8];
    __shared__ int   s_idx[256 * 8];

    // ---- Phase 1a: load 32 elements/thread (8x float4, front-batched) ----
    const float4* xr = reinterpret_cast<const float4*>(x + (size_t)n * QD);
    float4 v[8];
#pragma unroll
    for (int c = 0; c < 8; c++) v[c] = xr[c * 256 + t];

    // ---- Phase 1b: per-thread sorted top-8 under lex(val desc, idx asc).
    // ids arrive in ascending order + strict '>' comparisons => on equal
    // values, earlier (lower) index stays ahead: list is lex-sorted.
    float tv[8];
    int   ti[8];
#pragma unroll
    for (int r = 0; r < 8; r++) { tv[r] = -FLT_MAX; ti[r] = 0x7FFFFFFF; }

    auto ins = [&](float val, int id) {
        if (val > tv[7]) {
            tv[7] = val; ti[7] = id;
#pragma unroll
            for (int p = 7; p > 0; p--) {
                if (tv[p] > tv[p - 1]) {
                    float fv = tv[p]; tv[p] = tv[p - 1]; tv[p - 1] = fv;
                    int   fi = ti[p]; ti[p] = ti[p - 1]; ti[p - 1] = fi;
                }
            }
        }
    };

#pragma unroll
    for (int c = 0; c < 8; c++) {
        int base = 4 * (c * 256 + t);
        ins(v[c].x, base + 0);
        ins(v[c].y, base + 1);
        ins(v[c].z, base + 2);
        ins(v[c].w, base + 3);
    }

#pragma unroll
    for (int r = 0; r < 8; r++) { s_val[t * 8 + r] = tv[r]; s_idx[t * 8 + r] = ti[r]; }
    __syncthreads();

    // ---- Phase 1c: tree-merge 256 lex-sorted 8-lists -> global top-8 ----
    // Merge(a,b): L[i] = lexmax(a[i], b[7-i]) is the top-8 of the union and
    // is bitonic; the 3-stage bitonic merger sorts it (strict total order =>
    // standard proofs apply verbatim).
    for (int s = 128; s > 0; s >>= 1) {
        if (t < s) {
            float L[8]; int Li[8];
#pragma unroll
            for (int r = 0; r < 8; r++) {
                float av = s_val[t * 8 + r];       int ai = s_idx[t * 8 + r];
                float bv = s_val[(t + s) * 8 + (7 - r)];
                int   bi = s_idx[(t + s) * 8 + (7 - r)];
                bool p = (av > bv) || (av == bv && ai < bi);  // lex greater
                L[r]  = p ? av : bv;
                Li[r] = p ? ai : bi;
            }
#define CE(i, j)                                                          \
            {                                                             \
                bool sw = (L[j] > L[i]) || (L[j] == L[i] && Li[j] < Li[i]); \
                if (sw) {                                                 \
                    float fv = L[i]; L[i] = L[j]; L[j] = fv;              \
                    int   fi = Li[i]; Li[i] = Li[j]; Li[j] = fi;          \
                }                                                         \
            }
            CE(0, 4) CE(1, 5) CE(2, 6) CE(3, 7)
            CE(0, 2) CE(1, 3) CE(4, 6) CE(5, 7)
            CE(0, 1) CE(2, 3) CE(4, 5) CE(6, 7)
#undef CE
#pragma unroll
            for (int r = 0; r < 8; r++) { s_val[t * 8 + r] = L[r]; s_idx[t * 8 + r] = Li[r]; }
        }
        __syncthreads();
    }

    // ---- Phase 2: out[n, :] = sum_{j<8} wT[idx_j, :]  (coalesced float2).
    // List is value-descending == jax's summation order, so f32 rounding
    // matches the reference bit-for-bit up to fma contraction.
    int idx[8];
#pragma unroll
    for (int r = 0; r < 8; r++) idx[r] = s_idx[r];

    const float2* wT2 = reinterpret_cast<const float2*>(g_wT);
    float2 acc = make_float2(0.f, 0.f);
#pragma unroll
    for (int r = 0; r < 8; r++) {
        float2 w = wT2[(size_t)idx[r] * (ED / 2) + t];
        acc.x += w.x;
        acc.y += w.y;
    }
    reinterpret_cast<float2*>(out)[(size_t)n * (ED / 2) + t] = acc;
}

// ---------------------------------------------------------------------------
extern "C" void kernel_launch(void* const* d_in, const int* in_sizes, int n_in,
                              void* d_out, int out_size) {
    const float* x = (const float*)d_in[0];   // [NT, QD] f32
    const float* w = (const float*)d_in[1];   // [ED, QD] f32
    // d_in[2] = k (== 8, compile-time constant here)
    float* out = (float*)d_out;               // [NT, ED] f32

    dim3 tb(32, 8);
    dim3 tg(QD / 32, ED / 32);
    transpose_kernel<<<tg, tb>>>(w);
    topk_gather_kernel<<<NT, 256>>>(x, out);
}

// round 6
// speedup vs baseline: 2.1315x; 2.1315x over previous
#include <cuda_runtime.h>
#include <float.h>

#define QD 8192   // QUANT_DIM (codebook size)
#define ED 512    // EMBED_DIM
#define NT 8192   // N_TOKENS
#define CAP 1024  // candidate-list capacity (overflow -> exact serial fallback)

// Scratch: weight.T [QD, ED] = 16 MB. Static __device__ global (no alloc).
__device__ float g_wT[(size_t)QD * ED];

// ---------------------------------------------------------------------------
// Kernel 1: tiled transpose weight[ED, QD] -> g_wT[QD, ED]
// ---------------------------------------------------------------------------
__global__ void transpose_kernel(const float* __restrict__ w) {
    __shared__ float tile[32][33];  // +1 pad: conflict-free
    int qx = blockIdx.x * 32 + threadIdx.x;
    int ey = blockIdx.y * 32 + threadIdx.y;
#pragma unroll
    for (int j = 0; j < 32; j += 8)
        tile[threadIdx.y + j][threadIdx.x] = w[(size_t)(ey + j) * QD + qx];
    __syncthreads();
    int ex = blockIdx.y * 32 + threadIdx.x;
    int qy = blockIdx.x * 32 + threadIdx.y;
#pragma unroll
    for (int j = 0; j < 32; j += 8)
        g_wT[(size_t)(qy + j) * ED + ex] = tile[threadIdx.x][threadIdx.y + j];
}

// Strict total order lex(value desc, index asc) — matches jax.lax.top_k ties.
__device__ __forceinline__ bool lexgt(float av, int ai, float bv, int bi) {
    return (av > bv) || (av == bv && ai < bi);
}

// ---------------------------------------------------------------------------
// Kernel 2: per-token top-8 (threshold prefilter) + gather-sum from g_wT.
// One block (256 threads) per token.
// ---------------------------------------------------------------------------
__global__ __launch_bounds__(256) void topk_gather_kernel(
    const float* __restrict__ x, float* __restrict__ out) {
    const int n = blockIdx.x;
    const int t = threadIdx.x;

    __shared__ float s_max[256];
    __shared__ float s_lv[CAP];
    __shared__ int   s_li[CAP];
    __shared__ int   s_cnt;
    __shared__ float s_T8;
    __shared__ int   s_fin[8];

    const float4* xr = reinterpret_cast<const float4*>(x + (size_t)n * QD);
    if (t == 0) s_cnt = 0;

    // ---- Phase 1: per-thread max over 32 elems (pure FMNMX, keep group maxes)
    float gmax[4];
#pragma unroll
    for (int c = 0; c < 4; c++) {
        float4 a = xr[(2 * c) * 256 + t];
        float4 b = xr[(2 * c + 1) * 256 + t];
        float m0 = fmaxf(fmaxf(a.x, a.y), fmaxf(a.z, a.w));
        float m1 = fmaxf(fmaxf(b.x, b.y), fmaxf(b.z, b.w));
        gmax[c] = fmaxf(m0, m1);
    }
    float tmax = fmaxf(fmaxf(gmax[0], gmax[1]), fmaxf(gmax[2], gmax[3]));
    s_max[t] = tmax;
    __syncthreads();

    // ---- Phase 2 (warp 0): T8 = 8th-largest of the 256 thread maxima.
    // Provably T8 <= true 8th-largest element value: the 8 threads owning the
    // top-8 maxima hold 8 distinct elements >= T8.
    if (t < 32) {
        float m[8];
#pragma unroll
        for (int j = 0; j < 8; j++) m[j] = s_max[j * 32 + t];
        // Batcher odd-even mergesort-8, descending (19 CEs, value-only).
#define VCE(i, j) { float lo = fminf(m[i], m[j]); m[i] = fmaxf(m[i], m[j]); m[j] = lo; }
        VCE(0, 1) VCE(2, 3) VCE(4, 5) VCE(6, 7)
        VCE(0, 2) VCE(1, 3) VCE(4, 6) VCE(5, 7)
        VCE(1, 2) VCE(5, 6)
        VCE(0, 4) VCE(1, 5) VCE(2, 6) VCE(3, 7)
        VCE(2, 4) VCE(3, 5)
        VCE(1, 2) VCE(3, 4) VCE(5, 6)
#undef VCE
        // 5 xor-shuffle bitonic merges: every lane ends with global top-8.
#pragma unroll
        for (int s = 1; s < 32; s <<= 1) {
            float p[8];
#pragma unroll
            for (int r = 0; r < 8; r++) p[r] = __shfl_xor_sync(0xffffffffu, m[r], s);
            float L[8];
#pragma unroll
            for (int r = 0; r < 8; r++) L[r] = fmaxf(m[r], p[7 - r]);
#define VCE2(i, j) { float lo = fminf(L[i], L[j]); L[i] = fmaxf(L[i], L[j]); L[j] = lo; }
            VCE2(0, 4) VCE2(1, 5) VCE2(2, 6) VCE2(3, 7)
            VCE2(0, 2) VCE2(1, 3) VCE2(4, 6) VCE2(5, 7)
            VCE2(0, 1) VCE2(2, 3) VCE2(4, 5) VCE2(6, 7)
#undef VCE2
#pragma unroll
            for (int r = 0; r < 8; r++) m[r] = L[r];
        }
        if (t == 0) s_T8 = m[7];
    }
    __syncthreads();
    const float T8 = s_T8;

    // ---- Phase 3: collect candidates >= T8 (rare path; reload from L2) ----
    if (tmax >= T8) {
#pragma unroll
        for (int c = 0; c < 4; c++) {
            if (gmax[c] >= T8) {
                float4 a = __ldg(&xr[(2 * c) * 256 + t]);
                float4 b = __ldg(&xr[(2 * c + 1) * 256 + t]);
                int ia = 4 * ((2 * c) * 256 + t);
                int ib = 4 * ((2 * c + 1) * 256 + t);
                float va[8] = {a.x, a.y, a.z, a.w, b.x, b.y, b.z, b.w};
                int   id[8] = {ia, ia + 1, ia + 2, ia + 3, ib, ib + 1, ib + 2, ib + 3};
#pragma unroll
                for (int j = 0; j < 8; j++) {
                    if (va[j] >= T8) {
                        int pos = atomicAdd(&s_cnt, 1);
                        if (pos < CAP) { s_lv[pos] = va[j]; s_li[pos] = id[j]; }
                    }
                }
            }
        }
    }
    __syncthreads();

    const int C = s_cnt;  // >= 8 guaranteed (>= 8 elements >= T8 exist)
    if (C <= CAP) {
        // ---- Phase 4 (warp 0): exact lex top-8 over the tiny candidate list
        if (t < 32) {
            float tv[8]; int ti[8];
#pragma unroll
            for (int r = 0; r < 8; r++) { tv[r] = -FLT_MAX; ti[r] = 0x7FFFFFFF; }
            for (int i = t; i < C; i += 32) {
                float v = s_lv[i]; int id = s_li[i];
                if (lexgt(v, id, tv[7], ti[7])) {
                    tv[7] = v; ti[7] = id;
#pragma unroll
                    for (int p = 7; p > 0; p--) {
                        if (lexgt(tv[p], ti[p], tv[p - 1], ti[p - 1])) {
                            float fv = tv[p]; tv[p] = tv[p - 1]; tv[p - 1] = fv;
                            int   fi = ti[p]; ti[p] = ti[p - 1]; ti[p - 1] = fi;
                        }
                    }
                }
            }
            // xor-shuffle merge with lex order.
#pragma unroll
            for (int s = 1; s < 32; s <<= 1) {
                float pv[8]; int pi[8];
#pragma unroll
                for (int r = 0; r < 8; r++) {
                    pv[r] = __shfl_xor_sync(0xffffffffu, tv[r], s);
                    pi[r] = __shfl_xor_sync(0xffffffffu, ti[r], s);
                }
                float L[8]; int Li[8];
#pragma unroll
                for (int r = 0; r < 8; r++) {
                    bool p = lexgt(tv[r], ti[r], pv[7 - r], pi[7 - r]);
                    L[r]  = p ? tv[r] : pv[7 - r];
                    Li[r] = p ? ti[r] : pi[7 - r];
                }
#define LCE(i, j)                                                       \
                {                                                       \
                    if (lexgt(L[j], Li[j], L[i], Li[i])) {              \
                        float fv = L[i]; L[i] = L[j]; L[j] = fv;        \
                        int   fi = Li[i]; Li[i] = Li[j]; Li[j] = fi;    \
                    }                                                   \
                }
                LCE(0, 4) LCE(1, 5) LCE(2, 6) LCE(3, 7)
                LCE(0, 2) LCE(1, 3) LCE(4, 6) LCE(5, 7)
                LCE(0, 1) LCE(2, 3) LCE(4, 5) LCE(6, 7)
#undef LCE
#pragma unroll
                for (int r = 0; r < 8; r++) { tv[r] = L[r]; ti[r] = Li[r]; }
            }
            // All lanes hold the identical value-descending top-8.
            if (t < 8) s_fin[t] = ti[t];
        }
    } else {
        // Overflow fallback: exact serial scan (never taken on this data).
        if (t == 0) {
            float tv[8]; int ti[8];
#pragma unroll
            for (int r = 0; r < 8; r++) { tv[r] = -FLT_MAX; ti[r] = 0x7FFFFFFF; }
            const float* xrow = x + (size_t)n * QD;
            for (int i = 0; i < QD; i++) {
                float v = xrow[i];
                if (lexgt(v, i, tv[7], ti[7])) {
                    tv[7] = v; ti[7] = i;
#pragma unroll
                    for (int p = 7; p > 0; p--) {
                        if (lexgt(tv[p], ti[p], tv[p - 1], ti[p - 1])) {
                            float fv = tv[p]; tv[p] = tv[p - 1]; tv[p - 1] = fv;
                            int   fi = ti[p]; ti[p] = ti[p - 1]; ti[p - 1] = fi;
                        }
                    }
                }
            }
#pragma unroll
            for (int r = 0; r < 8; r++) s_fin[r] = ti[r];
        }
    }
    __syncthreads();

    // ---- Phase 5: out[n, :] = sum_{j<8} wT[idx_j, :] (coalesced float2).
    // List is value-descending == jax's summation order.
    int idx[8];
#pragma unroll
    for (int r = 0; r < 8; r++) idx[r] = s_fin[r];

    const float2* wT2 = reinterpret_cast<const float2*>(g_wT);
    float2 acc = make_float2(0.f, 0.f);
#pragma unroll
    for (int r = 0; r < 8; r++) {
        float2 w = wT2[(size_t)idx[r] * (ED / 2) + t];
        acc.x += w.x;
        acc.y += w.y;
    }
    reinterpret_cast<float2*>(out)[(size_t)n * (ED / 2) + t] = acc;
}

// ---------------------------------------------------------------------------
extern "C" void kernel_launch(void* const* d_in, const int* in_sizes, int n_in,
                              void* d_out, int out_size) {
    const float* x = (const float*)d_in[0];   // [NT, QD] f32
    const float* w = (const float*)d_in[1];   // [ED, QD] f32
    // d_in[2] = k (== 8, compile-time constant here)
    float* out = (float*)d_out;               // [NT, ED] f32

    dim3 tb(32, 8);
    dim3 tg(QD / 32, ED / 32);
    transpose_kernel<<<tg, tb>>>(w);
    topk_gather_kernel<<<NT, 256>>>(x, out);
}